// round 1
// baseline (speedup 1.0000x reference)
#include <cuda_runtime.h>

// SNN forward: T=1000, B=8192, I=9, H=96, O=3
// out = concat(spk2_rec[T,B,O], mem2_rec[T,B,O]) fp32
//
// Mapping: 8 lanes per batch element (group), each lane owns 12 hidden units.
// All heavy math in packed fp32x2 (Blackwell fma.rn.f32x2), weights in registers.

#define T_STEPS 1000
#define BATCH   8192
#define NIN     9
#define NHID    96
#define NOUT    3
#define BETA    0.92f

typedef unsigned long long u64;

__device__ __forceinline__ u64 pk2(float lo, float hi) {
    u64 r; asm("mov.b64 %0,{%1,%2};" : "=l"(r) : "f"(lo), "f"(hi)); return r;
}
__device__ __forceinline__ void upk2(u64 v, float& a, float& b) {
    asm("mov.b64 {%0,%1},%2;" : "=f"(a), "=f"(b) : "l"(v));
}
__device__ __forceinline__ u64 ffma2(u64 a, u64 b, u64 c) {
    u64 d; asm("fma.rn.f32x2 %0,%1,%2,%3;" : "=l"(d) : "l"(a), "l"(b), "l"(c)); return d;
}
__device__ __forceinline__ u64 fadd2(u64 a, u64 b) {
    u64 d; asm("add.rn.f32x2 %0,%1,%2;" : "=l"(d) : "l"(a), "l"(b)); return d;
}
__device__ __forceinline__ u64 fmul2(u64 a, u64 b) {
    u64 d; asm("mul.rn.f32x2 %0,%1,%2;" : "=l"(d) : "l"(a), "l"(b)); return d;
}

__global__ void __launch_bounds__(128, 2) snn_kernel(
    const float* __restrict__ x,
    const float* __restrict__ W1,
    const float* __restrict__ b1,
    const float* __restrict__ W2,
    const float* __restrict__ b2,
    float* __restrict__ out)
{
    const int lane = threadIdx.x & 31;
    const int gwarp = (blockIdx.x * blockDim.x + threadIdx.x) >> 5;
    const int grp  = lane >> 3;       // 0..3 : which batch within the warp
    const int hl   = lane & 7;        // 0..7 : which hidden slice
    const int b    = gwarp * 4 + grp; // batch element
    const int hb   = hl * 12;         // first hidden unit of this lane

    // ---- load weights into registers (f32x2 packed over h pairs) ----
    u64 w1p[6][9];
    #pragma unroll
    for (int j = 0; j < 6; j++)
        #pragma unroll
        for (int i = 0; i < 9; i++)
            w1p[j][i] = pk2(W1[(hb + 2*j) * NIN + i], W1[(hb + 2*j + 1) * NIN + i]);

    u64 w2p[3][6];
    #pragma unroll
    for (int o = 0; o < 3; o++)
        #pragma unroll
        for (int j = 0; j < 6; j++)
            w2p[o][j] = pk2(W2[o * NHID + hb + 2*j], W2[o * NHID + hb + 2*j + 1]);

    u64 b1p[6];
    #pragma unroll
    for (int j = 0; j < 6; j++)
        b1p[j] = pk2(b1[hb + 2*j], b1[hb + 2*j + 1]);

    float bb2_0 = b2[0], bb2_1 = b2[1], bb2_2 = b2[2];

    // ---- state ----
    u64 mem1p[6], spk1p[6];
    #pragma unroll
    for (int j = 0; j < 6; j++) { mem1p[j] = 0ull; spk1p[j] = 0ull; }
    float mem2v0 = 0.f, mem2v1 = 0.f, mem2v2 = 0.f;
    float spk2v0 = 0.f, spk2v1 = 0.f, spk2v2 = 0.f;

    const u64 BET2 = pk2(BETA, BETA);
    const u64 NEG1 = pk2(-1.0f, -1.0f);

    const size_t xstride = (size_t)BATCH * NIN;
    size_t xoff = (size_t)b * NIN;

    float xc[9];
    #pragma unroll
    for (int i = 0; i < 9; i++) xc[i] = x[xoff + i];

    float* __restrict__ out_spk = out;
    float* __restrict__ out_mem = out + (size_t)T_STEPS * BATCH * NOUT;

    for (int t = 0; t < T_STEPS; t++) {
        // prefetch next timestep's input (clamped on last iter)
        float xn[9];
        size_t xoffn = (t + 1 < T_STEPS) ? (xoff + xstride) : xoff;
        #pragma unroll
        for (int i = 0; i < 9; i++) xn[i] = x[xoffn + i];

        // broadcast x into f32x2 pairs
        u64 xp[9];
        #pragma unroll
        for (int i = 0; i < 9; i++) xp[i] = pk2(xc[i], xc[i]);

        // ---- layer 1: cur1 = x @ W1^T + b1 ; mem1 = beta*mem1 + cur1 - spk1_prev ----
        #pragma unroll
        for (int j = 0; j < 6; j++) {
            u64 a = fmul2(w1p[j][0], xp[0]);
            #pragma unroll
            for (int i = 1; i < 9; i++) a = ffma2(w1p[j][i], xp[i], a);
            a = fadd2(a, b1p[j]);               // + b1
            a = ffma2(BET2, mem1p[j], a);        // beta*mem1 + cur1
            mem1p[j] = ffma2(spk1p[j], NEG1, a); // - rst (= prev spike) * 1.0
        }

        // ---- spikes + layer-2 partial sums ----
        u64 c0 = 0ull, c1 = 0ull, c2 = 0ull;
        #pragma unroll
        for (int j = 0; j < 6; j++) {
            float ma, mb;
            upk2(mem1p[j], ma, mb);
            float sa = (ma > 1.0f) ? 1.0f : 0.0f;
            float sb = (mb > 1.0f) ? 1.0f : 0.0f;
            u64 sp = pk2(sa, sb);
            spk1p[j] = sp;
            c0 = ffma2(sp, w2p[0][j], c0);
            c1 = ffma2(sp, w2p[1][j], c1);
            c2 = ffma2(sp, w2p[2][j], c2);
        }
        float cur0, cur1v, cur2v;
        { float a, bv;
          upk2(c0, a, bv); cur0  = a + bv;
          upk2(c1, a, bv); cur1v = a + bv;
          upk2(c2, a, bv); cur2v = a + bv; }

        // butterfly all-reduce within the 8-lane group
        #pragma unroll
        for (int d = 1; d < 8; d <<= 1) {
            cur0  += __shfl_xor_sync(0xffffffffu, cur0,  d);
            cur1v += __shfl_xor_sync(0xffffffffu, cur1v, d);
            cur2v += __shfl_xor_sync(0xffffffffu, cur2v, d);
        }

        // ---- layer 2 membrane update ----
        float m0 = fmaf(BETA, mem2v0, cur0  + bb2_0) - spk2v0;
        float m1 = fmaf(BETA, mem2v1, cur1v + bb2_1) - spk2v1;
        float m2 = fmaf(BETA, mem2v2, cur2v + bb2_2) - spk2v2;
        mem2v0 = m0; mem2v1 = m1; mem2v2 = m2;
        spk2v0 = (m0 > 1.0f) ? 1.0f : 0.0f;
        spk2v1 = (m1 > 1.0f) ? 1.0f : 0.0f;
        spk2v2 = (m2 > 1.0f) ? 1.0f : 0.0f;

        // ---- store: lanes 0..2 write spk2, lanes 3..5 write mem2 (values replicated) ----
        size_t ob = ((size_t)t * BATCH + b) * NOUT;
        if (hl < 3) {
            float v = (hl == 0) ? spk2v0 : ((hl == 1) ? spk2v1 : spk2v2);
            out_spk[ob + hl] = v;
        } else if (hl < 6) {
            float v = (hl == 3) ? mem2v0 : ((hl == 4) ? mem2v1 : mem2v2);
            out_mem[ob + (hl - 3)] = v;
        }

        #pragma unroll
        for (int i = 0; i < 9; i++) xc[i] = xn[i];
        xoff += xstride;
    }
}

extern "C" void kernel_launch(void* const* d_in, const int* in_sizes, int n_in,
                              void* d_out, int out_size) {
    const float* x  = (const float*)d_in[0];
    const float* W1 = (const float*)d_in[1];
    const float* b1 = (const float*)d_in[2];
    const float* W2 = (const float*)d_in[3];
    const float* b2 = (const float*)d_in[4];
    float* out = (float*)d_out;

    // 8192 batches * 8 lanes = 65536 threads; 128 threads/CTA -> 512 CTAs
    snn_kernel<<<512, 128>>>(x, W1, b1, W2, b2, out);
}